// round 7
// baseline (speedup 1.0000x reference)
#include <cuda_runtime.h>
#include <cuda_bf16.h>
#include <cstdint>
#include <math_constants.h>

#define B_ 64
#define L_ 1024
#define P_ 2047
#define SB 72          // smem tile stride (bf16 elems) = 144B rows (16B-aligned for ldmatrix)
#define RG 66          // G ring stride (floats)
#define NS 16

#define T128 (128 * SB * 2)
#define T64  (64 * SB * 2)
#define O_QH 0
#define O_QL (O_QH + T128)
#define O_RH (O_QL + T128)
#define O_RL (O_RH + T128)
#define O_KH (O_RL + T128)
#define O_KL (O_KH + T64)
#define O_PH (O_KL + T64)
#define O_PL (O_PH + T64)
#define O_G  (O_PL + T64)
#define GSZ  (128 * RG)
#define O_ST (O_G + 3 * GSZ * 4)
#define O_MC (O_ST + 128 * 2 * 8)
#define SMEMB (O_MC + 16)

__device__ __forceinline__ uint32_t smem_u32(const void* p) {
    uint32_t a;
    asm("{ .reg .u64 t; cvta.to.shared.u64 t, %1; cvt.u32.u64 %0, t; }" : "=r"(a) : "l"(p));
    return a;
}
#define LDSM4(r, a) \
    asm volatile("ldmatrix.sync.aligned.m8n8.x4.shared.b16 {%0,%1,%2,%3}, [%4];" \
        : "=r"((r)[0]), "=r"((r)[1]), "=r"((r)[2]), "=r"((r)[3]) : "r"(a))
#define LDSM2(r, a) \
    asm volatile("ldmatrix.sync.aligned.m8n8.x2.shared.b16 {%0,%1}, [%2];" \
        : "=r"((r)[0]), "=r"((r)[1]) : "r"(a))
#define LDSM2T(r, a) \
    asm volatile("ldmatrix.sync.aligned.m8n8.x2.trans.shared.b16 {%0,%1}, [%2];" \
        : "=r"((r)[0]), "=r"((r)[1]) : "r"(a))
#define MMA(c, a, b) \
    asm volatile("mma.sync.aligned.m16n8k16.row.col.f32.bf16.bf16.f32 " \
        "{%0,%1,%2,%3}, {%4,%5,%6,%7}, {%8,%9}, {%0,%1,%2,%3};" \
        : "+f"((c)[0]), "+f"((c)[1]), "+f"((c)[2]), "+f"((c)[3]) \
        : "r"((a)[0]), "r"((a)[1]), "r"((a)[2]), "r"((a)[3]), "r"((b)[0]), "r"((b)[1]))

__device__ __forceinline__ uint32_t pk2(float a, float b) {
    return (uint32_t)__bfloat16_as_ushort(__float2bfloat16(a)) |
           ((uint32_t)__bfloat16_as_ushort(__float2bfloat16(b)) << 16);
}
__device__ __forceinline__ void spl(char* sm, int offH, int offL, int eo, float4 v) {
    float hx = __bfloat162float(__float2bfloat16(v.x));
    float hy = __bfloat162float(__float2bfloat16(v.y));
    float hz = __bfloat162float(__float2bfloat16(v.z));
    float hw = __bfloat162float(__float2bfloat16(v.w));
    *(uint2*)(sm + offH + eo * 2) = make_uint2(pk2(v.x, v.y), pk2(v.z, v.w));
    *(uint2*)(sm + offL + eo * 2) =
        make_uint2(pk2(v.x - hx, v.y - hy), pk2(v.z - hz, v.w - hw));
}
__device__ __forceinline__ void merge_ms(float& m, float& s, float om, float os) {
    float nm = fmaxf(m, om);
    float base = (nm == -CUDART_INF_F) ? 0.f : nm;
    s = s * __expf(m - base) + os * __expf(om - base);
    m = nm;
}

__global__ __launch_bounds__(256, 1)
void fused_mma_kernel(const float* __restrict__ q, const float* __restrict__ kk,
                      const float* __restrict__ v, const float* __restrict__ pos,
                      const char* __restrict__ maskp, float* __restrict__ out,
                      float* __restrict__ attn) {
    extern __shared__ char sm[];
    const uint32_t sb = smem_u32(sm);
    const int tid = threadIdx.x;
    const int lane = tid & 31, w = tid >> 5;
    const int wr = w >> 1, wc = w & 1;           // 4 warps in m (32 rows), 2 in n (32 cols)
    const int b = blockIdx.y, l0 = blockIdx.x * 128;

    const float* qb = q + (size_t)b * L_ * 64;
    const float* kb = kk + (size_t)b * L_ * 64;
    const float* vb = v + (size_t)b * L_ * 64;
    const float* pb = pos + (size_t)b * P_ * 64;

    float* ring = (float*)(sm + O_G);
    float2* st = (float2*)(sm + O_ST);
    int* cnt = (int*)(sm + O_MC);

    // ---- mask dtype detection (first 8KB) ----
    if (tid < 2) cnt[tid] = 0;
    __syncthreads();
    {
        int c0 = 0, c1 = 0;
        #pragma unroll
        for (int e = 0; e < 2; e++) {
            uint4 u = ((const uint4*)maskp)[tid * 2 + e];
            uint32_t ws[4] = {u.x, u.y, u.z, u.w};
            #pragma unroll
            for (int wd = 0; wd < 4; wd++) {
                c0 += ((ws[wd] & 0x000000ffu) != 0);
                c1 += ((ws[wd] & 0x0000ff00u) != 0);
            }
        }
        if (c0) atomicAdd(&cnt[0], c0);
        if (c1) atomicAdd(&cnt[1], c1);
    }

    // ---- prologue loads: Q/R 128 rows; K0, P win0 ----
    #pragma unroll
    for (int e = 0; e < 8; e++) {
        int f = tid + e * 256;            // 2048 float4 chunks
        int r = f >> 4, c4 = (f & 15) << 2;
        float4 a = *(const float4*)(qb + (size_t)(l0 + r) * 64 + c4);
        a.x *= .125f; a.y *= .125f; a.z *= .125f; a.w *= .125f;
        spl(sm, O_QH, O_QL, r * SB + c4, a);
        float4 rr = *(const float4*)(qb + (size_t)(L_ - 1 - (l0 + r)) * 64 + c4);
        rr.x *= .125f; rr.y *= .125f; rr.z *= .125f; rr.w *= .125f;
        spl(sm, O_RH, O_RL, r * SB + c4, rr);
    }
    #pragma unroll
    for (int e = 0; e < 4; e++) {
        int f = tid + e * 256;
        int r = f >> 4, c4 = (f & 15) << 2;
        float4 kv = *(const float4*)(kb + (size_t)r * 64 + c4);
        spl(sm, O_KH, O_KL, r * SB + c4, kv);
        int pr = l0 + r; if (pr > P_ - 1) pr = P_ - 1;
        float4 pv = *(const float4*)(pb + (size_t)pr * 64 + c4);
        spl(sm, O_PH, O_PL, r * SB + c4, pv);
    }
    __syncthreads();
    const int mode = (cnt[0] > 0 && cnt[1] > 0) ? 0 : 1;

    auto adA = [&](int off, int mt, int kc) -> uint32_t {
        return sb + off + ((32 * wr + 16 * mt + (lane & 15)) * SB + kc * 16 + (lane >> 4) * 8) * 2;
    };
    auto adB = [&](int off, int nf, int kc) -> uint32_t {
        return sb + off + ((32 * wc + 8 * nf + (lane & 7)) * SB + kc * 16 + ((lane >> 3) & 1) * 8) * 2;
    };
    auto adBT = [&](int off, int nf, int kc) -> uint32_t {
        return sb + off + ((kc * 16 + (lane & 15)) * SB + 32 * wc + 8 * nf) * 2;
    };
    // m32n32k64 3-product split-bf16 GEMM per warp
    auto gemm3 = [&](int oAh, int oAl, int oBh, int oBl, float acc[2][4][4], bool trans) {
        #pragma unroll
        for (int kc = 0; kc < 4; kc++) {
            uint32_t Ah[2][4], Al[2][4];
            #pragma unroll
            for (int mt = 0; mt < 2; mt++) { LDSM4(Ah[mt], adA(oAh, mt, kc)); LDSM4(Al[mt], adA(oAl, mt, kc)); }
            #pragma unroll
            for (int nf = 0; nf < 4; nf++) {
                uint32_t Bf[2];
                if (trans) LDSM2T(Bf, adBT(oBh, nf, kc)); else LDSM2(Bf, adB(oBh, nf, kc));
                MMA(acc[0][nf], Ah[0], Bf); MMA(acc[1][nf], Ah[1], Bf);
                MMA(acc[0][nf], Al[0], Bf); MMA(acc[1][nf], Al[1], Bf);
                if (trans) LDSM2T(Bf, adBT(oBl, nf, kc)); else LDSM2(Bf, adB(oBl, nf, kc));
                MMA(acc[0][nf], Ah[0], Bf); MMA(acc[1][nf], Ah[1], Bf);
            }
        }
    };
    const int q4 = lane >> 2, c2 = lane & 3;

    auto ring_store = [&](float acc[2][4][4], int slot) {
        float* gn = ring + slot * GSZ;
        #pragma unroll
        for (int mt = 0; mt < 2; mt++)
            #pragma unroll
            for (int nf = 0; nf < 4; nf++) {
                int j0 = 32 * wc + 8 * nf + 2 * c2;
                #pragma unroll
                for (int h = 0; h < 2; h++) {
                    int i = 32 * wr + 16 * mt + q4 + 8 * h;
                    *(float2*)(gn + i * RG + j0) = make_float2(acc[mt][nf][2 * h], acc[mt][nf][2 * h + 1]);
                }
            }
    };
    auto load_P = [&](int win) {
        #pragma unroll
        for (int e = 0; e < 4; e++) {
            int f = tid + e * 256;
            int r = f >> 4, c4 = (f & 15) << 2;
            int pr = l0 + 64 * win + r; if (pr > P_ - 1) pr = P_ - 1;
            float4 pv = *(const float4*)(pb + (size_t)pr * 64 + c4);
            spl(sm, O_PH, O_PL, r * SB + c4, pv);
        }
    };

    // ---- prologue G0, G1 ----
    {
        float accG[2][4][4] = {};
        gemm3(O_RH, O_RL, O_PH, O_PL, accG, false);
        __syncthreads();
        ring_store(accG, 0);
        load_P(1);
        __syncthreads();
    }
    {
        float accG[2][4][4] = {};
        gemm3(O_RH, O_RL, O_PH, O_PL, accG, false);
        __syncthreads();
        ring_store(accG, 1);
        load_P(2);
        __syncthreads();
    }

    float run_m[2][2], run_s[2][2];
    #pragma unroll
    for (int mt = 0; mt < 2; mt++)
        #pragma unroll
        for (int h = 0; h < 2; h++) { run_m[mt][h] = -CUDART_INF_F; run_s[mt][h] = 0.f; }

    // ================= phase 1: logits =================
    for (int t = 0; t < NS; t++) {
        float accS[2][4][4] = {};
        float accG[2][4][4] = {};
        gemm3(O_QH, O_QL, O_KH, O_KL, accS, false);
        gemm3(O_RH, O_RL, O_PH, O_PL, accG, false);
        __syncthreads();                       // MMA reads done
        ring_store(accG, (t + 2) % 3);
        if (t < NS - 1) {
            #pragma unroll
            for (int e = 0; e < 4; e++) {
                int f = tid + e * 256;
                int r = f >> 4, c4 = (f & 15) << 2;
                float4 kv = *(const float4*)(kb + (size_t)((t + 1) * 64 + r) * 64 + c4);
                spl(sm, O_KH, O_KL, r * SB + c4, kv);
            }
        }
        load_P(t + 3);
        __syncthreads();                       // ring + new tiles visible
        // epilogue
        const float* g0 = ring + (t % 3) * GSZ;
        const float* g1 = ring + ((t + 1) % 3) * GSZ;
        const float* g2 = ring + ((t + 2) % 3) * GSZ;
        #pragma unroll
        for (int mt = 0; mt < 2; mt++) {
            float xv[2][8];
            #pragma unroll
            for (int nf = 0; nf < 4; nf++) {
                int j0 = 32 * wc + 8 * nf + 2 * c2;
                #pragma unroll
                for (int h = 0; h < 2; h++) {
                    int i = 32 * wr + 16 * mt + q4 + 8 * h;
                    int s0 = i + j0, s1 = s0 + 1;
                    const float* ga = (s0 < 64) ? g0 : ((s0 < 128) ? g1 : g2);
                    const float* gbq = (s1 < 64) ? g0 : ((s1 < 128) ? g1 : g2);
                    float x0 = accS[mt][nf][2 * h] + ga[i * RG + (s0 & 63)];
                    float x1 = accS[mt][nf][2 * h + 1] + gbq[i * RG + (s1 & 63)];
                    size_t gidx = ((size_t)b * L_ + l0 + i) * L_ + t * 64 + j0;
                    if (mode == 0) {
                        unsigned short mv = *(const unsigned short*)(maskp + gidx);
                        if (mv & 0x00ff) x0 = -CUDART_INF_F;
                        if (mv & 0xff00) x1 = -CUDART_INF_F;
                    } else {
                        uint2 mv = *(const uint2*)((const uint32_t*)maskp + gidx);
                        if (mv.x) x0 = -CUDART_INF_F;
                        if (mv.y) x1 = -CUDART_INF_F;
                    }
                    *(float2*)(attn + gidx) = make_float2(x0, x1);
                    xv[h][2 * nf] = x0; xv[h][2 * nf + 1] = x1;
                }
            }
            #pragma unroll
            for (int h = 0; h < 2; h++) {
                float lm = xv[h][0];
                #pragma unroll
                for (int j = 1; j < 8; j++) lm = fmaxf(lm, xv[h][j]);
                float nm = fmaxf(run_m[mt][h], lm);
                float base = (nm == -CUDART_INF_F) ? 0.f : nm;
                float es = 0.f;
                #pragma unroll
                for (int j = 0; j < 8; j++) es += __expf(xv[h][j] - base);
                run_s[mt][h] = run_s[mt][h] * __expf(run_m[mt][h] - base) + es;
                run_m[mt][h] = nm;
            }
        }
    }

    // ---- merge stats: quad lanes then across wc warps ----
    #pragma unroll
    for (int mt = 0; mt < 2; mt++)
        #pragma unroll
        for (int h = 0; h < 2; h++) {
            #pragma unroll
            for (int sft = 1; sft < 4; sft <<= 1) {
                float om = __shfl_xor_sync(0xffffffffu, run_m[mt][h], sft);
                float os = __shfl_xor_sync(0xffffffffu, run_s[mt][h], sft);
                merge_ms(run_m[mt][h], run_s[mt][h], om, os);
            }
            if (c2 == 0) {
                int i = 32 * wr + 16 * mt + q4 + 8 * h;
                st[i * 2 + wc] = make_float2(run_m[mt][h], run_s[mt][h]);
            }
        }
    __syncthreads();
    float mxu[2][2], inv[2][2];
    #pragma unroll
    for (int mt = 0; mt < 2; mt++)
        #pragma unroll
        for (int h = 0; h < 2; h++) {
            int i = 32 * wr + 16 * mt + q4 + 8 * h;
            float2 a = st[i * 2 + 0], bq = st[i * 2 + 1];
            float m = a.x, s = a.y;
            merge_ms(m, s, bq.x, bq.y);
            mxu[mt][h] = (m == -CUDART_INF_F) ? 0.f : m;
            inv[mt][h] = 1.f / s;
        }
    __syncthreads();

    // ================= phase 2: probs + O = P @ V =================
    float accO[2][4][4] = {};
    for (int t = 0; t < NS; t++) {
        #pragma unroll
        for (int mt = 0; mt < 2; mt++)
            #pragma unroll
            for (int nf = 0; nf < 4; nf++) {
                int j0 = 32 * wc + 8 * nf + 2 * c2;
                #pragma unroll
                for (int h = 0; h < 2; h++) {
                    int i = 32 * wr + 16 * mt + q4 + 8 * h;
                    size_t gidx = ((size_t)b * L_ + l0 + i) * L_ + t * 64 + j0;
                    float2 x = *(const float2*)(attn + gidx);
                    float p0 = __expf(x.x - mxu[mt][h]) * inv[mt][h];
                    float p1 = __expf(x.y - mxu[mt][h]) * inv[mt][h];
                    *(float2*)(attn + gidx) = make_float2(p0, p1);
                    float h0 = __bfloat162float(__float2bfloat16(p0));
                    float h1 = __bfloat162float(__float2bfloat16(p1));
                    *(uint32_t*)(sm + O_QH + (i * SB + j0) * 2) = pk2(p0, p1);
                    *(uint32_t*)(sm + O_QL + (i * SB + j0) * 2) = pk2(p0 - h0, p1 - h1);
                }
            }
        #pragma unroll
        for (int e = 0; e < 4; e++) {
            int f = tid + e * 256;
            int r = f >> 4, c4 = (f & 15) << 2;
            float4 vv = *(const float4*)(vb + (size_t)(t * 64 + r) * 64 + c4);
            spl(sm, O_KH, O_KL, r * SB + c4, vv);
        }
        __syncthreads();
        gemm3(O_QH, O_QL, O_KH, O_KL, accO, true);
        __syncthreads();
    }
    #pragma unroll
    for (int mt = 0; mt < 2; mt++)
        #pragma unroll
        for (int nf = 0; nf < 4; nf++) {
            int j0 = 32 * wc + 8 * nf + 2 * c2;
            #pragma unroll
            for (int h = 0; h < 2; h++) {
                int i = 32 * wr + 16 * mt + q4 + 8 * h;
                *(float2*)(out + ((size_t)b * L_ + l0 + i) * 64 + j0) =
                    make_float2(accO[mt][nf][2 * h], accO[mt][nf][2 * h + 1]);
            }
        }
}

extern "C" void kernel_launch(void* const* d_in, const int* in_sizes, int n_in,
                              void* d_out, int out_size) {
    const float* q = (const float*)d_in[0];
    const float* k = (const float*)d_in[1];
    const float* v = (const float*)d_in[2];
    const float* pos = (const float*)d_in[3];
    const char* msk = (const char*)d_in[4];
    float* out = (float*)d_out;
    float* attn = out + (size_t)B_ * L_ * 64;

    cudaFuncSetAttribute(fused_mma_kernel,
                         cudaFuncAttributeMaxDynamicSharedMemorySize, SMEMB);
    fused_mma_kernel<<<dim3(8, B_), 256, SMEMB>>>(q, k, v, pos, msk, out, attn);
}

// round 8
// speedup vs baseline: 1.0059x; 1.0059x over previous
#include <cuda_runtime.h>
#include <cuda_bf16.h>
#include <cstdint>
#include <math_constants.h>

#define B_ 64
#define L_ 1024
#define P_ 2047
#define SB 72          // smem tile stride (bf16) = 144B rows
#define RG 66          // G ring stride (floats)
#define NS 16

#define T64  (64 * SB * 2)
#define O_QH 0
#define O_QL (O_QH + T64)
#define O_RH (O_QL + T64)
#define O_RL (O_RH + T64)
#define O_KH (O_RL + T64)
#define O_KL (O_KH + T64)
#define O_PH (O_KL + T64)
#define O_PL (O_PH + T64)
#define O_G  (O_PL + T64)
#define GSZ  (64 * RG)
#define O_ST (O_G + 2 * GSZ * 4)
#define O_MC (O_ST + 64 * 2 * 8)
#define SMEMB (O_MC + 16)

__device__ __forceinline__ uint32_t smem_u32(const void* p) {
    uint32_t a;
    asm("{ .reg .u64 t; cvta.to.shared.u64 t, %1; cvt.u32.u64 %0, t; }" : "=r"(a) : "l"(p));
    return a;
}
#define LDSM4(r, a) \
    asm volatile("ldmatrix.sync.aligned.m8n8.x4.shared.b16 {%0,%1,%2,%3}, [%4];" \
        : "=r"((r)[0]), "=r"((r)[1]), "=r"((r)[2]), "=r"((r)[3]) : "r"(a))
#define LDSM2(r, a) \
    asm volatile("ldmatrix.sync.aligned.m8n8.x2.shared.b16 {%0,%1}, [%2];" \
        : "=r"((r)[0]), "=r"((r)[1]) : "r"(a))
#define LDSM2T(r, a) \
    asm volatile("ldmatrix.sync.aligned.m8n8.x2.trans.shared.b16 {%0,%1}, [%2];" \
        : "=r"((r)[0]), "=r"((r)[1]) : "r"(a))
#define MMA(c, a, b) \
    asm volatile("mma.sync.aligned.m16n8k16.row.col.f32.bf16.bf16.f32 " \
        "{%0,%1,%2,%3}, {%4,%5,%6,%7}, {%8,%9}, {%0,%1,%2,%3};" \
        : "+f"((c)[0]), "+f"((c)[1]), "+f"((c)[2]), "+f"((c)[3]) \
        : "r"((a)[0]), "r"((a)[1]), "r"((a)[2]), "r"((a)[3]), "r"((b)[0]), "r"((b)[1]))

__device__ __forceinline__ uint32_t pk2(float a, float b) {
    return (uint32_t)__bfloat16_as_ushort(__float2bfloat16(a)) |
           ((uint32_t)__bfloat16_as_ushort(__float2bfloat16(b)) << 16);
}
__device__ __forceinline__ void spl(char* sm, int offH, int offL, int eo, float4 v) {
    float hx = __bfloat162float(__float2bfloat16(v.x));
    float hy = __bfloat162float(__float2bfloat16(v.y));
    float hz = __bfloat162float(__float2bfloat16(v.z));
    float hw = __bfloat162float(__float2bfloat16(v.w));
    *(uint2*)(sm + offH + eo * 2) = make_uint2(pk2(v.x, v.y), pk2(v.z, v.w));
    *(uint2*)(sm + offL + eo * 2) =
        make_uint2(pk2(v.x - hx, v.y - hy), pk2(v.z - hz, v.w - hw));
}
__device__ __forceinline__ void merge_ms(float& m, float& s, float om, float os) {
    float nm = fmaxf(m, om);
    float base = (nm == -CUDART_INF_F) ? 0.f : nm;
    s = s * __expf(m - base) + os * __expf(om - base);
    m = nm;
}

__global__ __launch_bounds__(128)
void fused_mma_kernel(const float* __restrict__ q, const float* __restrict__ kk,
                      const float* __restrict__ v, const float* __restrict__ pos,
                      const char* __restrict__ maskp, float* __restrict__ out,
                      float* __restrict__ attn) {
    extern __shared__ char sm[];
    const uint32_t sb = smem_u32(sm);
    const int tid = threadIdx.x;
    const int lane = tid & 31, w = tid >> 5;
    const int wr = w >> 1, wc = w & 1;           // 2 warps in m (32 rows each), 2 in n
    const int b = blockIdx.y, l0 = blockIdx.x * 64;

    const float* qb = q + (size_t)b * L_ * 64;
    const float* kb = kk + (size_t)b * L_ * 64;
    const float* vb = v + (size_t)b * L_ * 64;
    const float* pb = pos + (size_t)b * P_ * 64;

    float* ring = (float*)(sm + O_G);
    float2* st = (float2*)(sm + O_ST);
    int* cnt = (int*)(sm + O_MC);

    // ---- mask dtype detection (first 8KB) ----
    if (tid < 2) cnt[tid] = 0;
    __syncthreads();
    {
        int c0 = 0, c1 = 0;
        #pragma unroll
        for (int e = 0; e < 4; e++) {
            uint4 u = ((const uint4*)maskp)[tid * 4 + e];
            uint32_t ws[4] = {u.x, u.y, u.z, u.w};
            #pragma unroll
            for (int wd = 0; wd < 4; wd++) {
                c0 += ((ws[wd] & 0x000000ffu) != 0);
                c1 += ((ws[wd] & 0x0000ff00u) != 0);
            }
        }
        if (c0) atomicAdd(&cnt[0], c0);
        if (c1) atomicAdd(&cnt[1], c1);
    }

    // ---- prologue loads: Q, R (scaled 1/8), K0, P win0 ----
    #pragma unroll
    for (int e = 0; e < 8; e++) {
        int f = tid + e * 128;             // 1024 float4 chunks per 64-row tile
        int r = f >> 4, c4 = (f & 15) << 2;
        float4 a = *(const float4*)(qb + (size_t)(l0 + r) * 64 + c4);
        a.x *= .125f; a.y *= .125f; a.z *= .125f; a.w *= .125f;
        spl(sm, O_QH, O_QL, r * SB + c4, a);
        float4 rr = *(const float4*)(qb + (size_t)(L_ - 1 - (l0 + r)) * 64 + c4);
        rr.x *= .125f; rr.y *= .125f; rr.z *= .125f; rr.w *= .125f;
        spl(sm, O_RH, O_RL, r * SB + c4, rr);
        float4 kv = *(const float4*)(kb + (size_t)r * 64 + c4);
        spl(sm, O_KH, O_KL, r * SB + c4, kv);
        int pr = l0 + r; if (pr > P_ - 1) pr = P_ - 1;
        float4 pv = *(const float4*)(pb + (size_t)pr * 64 + c4);
        spl(sm, O_PH, O_PL, r * SB + c4, pv);
    }
    __syncthreads();
    const int mode = (cnt[0] > 0 && cnt[1] > 0) ? 0 : 1;

    auto adA = [&](int off, int mt, int kc) -> uint32_t {
        return sb + off + ((32 * wr + 16 * mt + (lane & 15)) * SB + kc * 16 + (lane >> 4) * 8) * 2;
    };
    auto adB = [&](int off, int nf, int kc) -> uint32_t {
        return sb + off + ((32 * wc + 8 * nf + (lane & 7)) * SB + kc * 16 + ((lane >> 3) & 1) * 8) * 2;
    };
    auto adBT = [&](int off, int nf, int kc) -> uint32_t {
        return sb + off + ((kc * 16 + (lane & 15)) * SB + 32 * wc + 8 * nf) * 2;
    };
    // m32n32k64 3-product split-bf16 GEMM per warp
    auto gemm3 = [&](int oAh, int oAl, int oBh, int oBl, float acc[2][4][4], bool trans) {
        #pragma unroll
        for (int kc = 0; kc < 4; kc++) {
            uint32_t Ah[2][4], Al[2][4];
            #pragma unroll
            for (int mt = 0; mt < 2; mt++) { LDSM4(Ah[mt], adA(oAh, mt, kc)); LDSM4(Al[mt], adA(oAl, mt, kc)); }
            #pragma unroll
            for (int nf = 0; nf < 4; nf++) {
                uint32_t Bf[2];
                if (trans) LDSM2T(Bf, adBT(oBh, nf, kc)); else LDSM2(Bf, adB(oBh, nf, kc));
                MMA(acc[0][nf], Ah[0], Bf); MMA(acc[1][nf], Ah[1], Bf);
                MMA(acc[0][nf], Al[0], Bf); MMA(acc[1][nf], Al[1], Bf);
                if (trans) LDSM2T(Bf, adBT(oBl, nf, kc)); else LDSM2(Bf, adB(oBl, nf, kc));
                MMA(acc[0][nf], Ah[0], Bf); MMA(acc[1][nf], Ah[1], Bf);
            }
        }
    };
    const int q4 = lane >> 2, c2 = lane & 3;

    auto ring_store = [&](float acc[2][4][4], int slot) {
        float* gn = ring + slot * GSZ;
        #pragma unroll
        for (int mt = 0; mt < 2; mt++)
            #pragma unroll
            for (int nf = 0; nf < 4; nf++) {
                int j0 = 32 * wc + 8 * nf + 2 * c2;
                #pragma unroll
                for (int h = 0; h < 2; h++) {
                    int i = 32 * wr + 16 * mt + q4 + 8 * h;
                    *(float2*)(gn + i * RG + j0) = make_float2(acc[mt][nf][2 * h], acc[mt][nf][2 * h + 1]);
                }
            }
    };
    auto load_P = [&](int win) {
        #pragma unroll
        for (int e = 0; e < 8; e++) {
            int f = tid + e * 128;
            int r = f >> 4, c4 = (f & 15) << 2;
            int pr = l0 + 64 * win + r; if (pr > P_ - 1) pr = P_ - 1;
            float4 pv = *(const float4*)(pb + (size_t)pr * 64 + c4);
            spl(sm, O_PH, O_PL, r * SB + c4, pv);
        }
    };

    // ---- prologue G0 ----
    {
        float accG[2][4][4] = {};
        gemm3(O_RH, O_RL, O_PH, O_PL, accG, false);
        __syncthreads();
        ring_store(accG, 0);
        load_P(1);
        __syncthreads();
    }

    float run_m[2][2], run_s[2][2];
    #pragma unroll
    for (int mt = 0; mt < 2; mt++)
        #pragma unroll
        for (int h = 0; h < 2; h++) { run_m[mt][h] = -CUDART_INF_F; run_s[mt][h] = 0.f; }

    // ================= phase 1: logits =================
    for (int t = 0; t < NS; t++) {
        float accS[2][4][4] = {};
        float accG[2][4][4] = {};
        gemm3(O_QH, O_QL, O_KH, O_KL, accS, false);
        gemm3(O_RH, O_RL, O_PH, O_PL, accG, false);   // G_{t+1}
        __syncthreads();                       // MMA reads done
        ring_store(accG, (t + 1) & 1);
        if (t < NS - 1) {
            #pragma unroll
            for (int e = 0; e < 8; e++) {
                int f = tid + e * 128;
                int r = f >> 4, c4 = (f & 15) << 2;
                float4 kv = *(const float4*)(kb + (size_t)((t + 1) * 64 + r) * 64 + c4);
                spl(sm, O_KH, O_KL, r * SB + c4, kv);
            }
        }
        load_P(t + 2);
        __syncthreads();                       // ring + new tiles visible
        const float* gc = ring + (t & 1) * GSZ;
        const float* gn = ring + ((t + 1) & 1) * GSZ;
        #pragma unroll
        for (int mt = 0; mt < 2; mt++) {
            float xv[2][8];
            #pragma unroll
            for (int nf = 0; nf < 4; nf++) {
                int j0 = 32 * wc + 8 * nf + 2 * c2;
                #pragma unroll
                for (int h = 0; h < 2; h++) {
                    int i = 32 * wr + 16 * mt + q4 + 8 * h;
                    int s0 = i + j0, s1 = s0 + 1;
                    float x0 = accS[mt][nf][2 * h] + ((s0 < 64) ? gc : gn)[i * RG + (s0 & 63)];
                    float x1 = accS[mt][nf][2 * h + 1] + ((s1 < 64) ? gc : gn)[i * RG + (s1 & 63)];
                    size_t gidx = ((size_t)b * L_ + l0 + i) * L_ + t * 64 + j0;
                    if (mode == 0) {
                        unsigned short mv = *(const unsigned short*)(maskp + gidx);
                        if (mv & 0x00ff) x0 = -CUDART_INF_F;
                        if (mv & 0xff00) x1 = -CUDART_INF_F;
                    } else {
                        uint2 mv = *(const uint2*)((const uint32_t*)maskp + gidx);
                        if (mv.x) x0 = -CUDART_INF_F;
                        if (mv.y) x1 = -CUDART_INF_F;
                    }
                    *(float2*)(attn + gidx) = make_float2(x0, x1);
                    xv[h][2 * nf] = x0; xv[h][2 * nf + 1] = x1;
                }
            }
            #pragma unroll
            for (int h = 0; h < 2; h++) {
                float lm = xv[h][0];
                #pragma unroll
                for (int j = 1; j < 8; j++) lm = fmaxf(lm, xv[h][j]);
                float nm = fmaxf(run_m[mt][h], lm);
                float base = (nm == -CUDART_INF_F) ? 0.f : nm;
                float es = 0.f;
                #pragma unroll
                for (int j = 0; j < 8; j++) es += __expf(xv[h][j] - base);
                run_s[mt][h] = run_s[mt][h] * __expf(run_m[mt][h] - base) + es;
                run_m[mt][h] = nm;
            }
        }
    }

    // ---- merge stats: quad lanes then across the 2 wc warps ----
    #pragma unroll
    for (int mt = 0; mt < 2; mt++)
        #pragma unroll
        for (int h = 0; h < 2; h++) {
            #pragma unroll
            for (int sft = 1; sft < 4; sft <<= 1) {
                float om = __shfl_xor_sync(0xffffffffu, run_m[mt][h], sft);
                float os = __shfl_xor_sync(0xffffffffu, run_s[mt][h], sft);
                merge_ms(run_m[mt][h], run_s[mt][h], om, os);
            }
            if (c2 == 0) {
                int i = 32 * wr + 16 * mt + q4 + 8 * h;
                st[i * 2 + wc] = make_float2(run_m[mt][h], run_s[mt][h]);
            }
        }
    __syncthreads();
    float mxu[2][2], inv[2][2];
    #pragma unroll
    for (int mt = 0; mt < 2; mt++)
        #pragma unroll
        for (int h = 0; h < 2; h++) {
            int i = 32 * wr + 16 * mt + q4 + 8 * h;
            float2 a = st[i * 2 + 0], bq = st[i * 2 + 1];
            float m = a.x, s = a.y;
            merge_ms(m, s, bq.x, bq.y);
            mxu[mt][h] = (m == -CUDART_INF_F) ? 0.f : m;
            inv[mt][h] = 1.f / s;
        }
    __syncthreads();

    // ================= phase 2: probs + O = P @ V =================
    float accO[2][4][4] = {};
    for (int t = 0; t < NS; t++) {
        #pragma unroll
        for (int mt = 0; mt < 2; mt++)
            #pragma unroll
            for (int nf = 0; nf < 4; nf++) {
                int j0 = 32 * wc + 8 * nf + 2 * c2;
                #pragma unroll
                for (int h = 0; h < 2; h++) {
                    int i = 32 * wr + 16 * mt + q4 + 8 * h;
                    size_t gidx = ((size_t)b * L_ + l0 + i) * L_ + t * 64 + j0;
                    float2 x = *(const float2*)(attn + gidx);
                    float p0 = __expf(x.x - mxu[mt][h]) * inv[mt][h];
                    float p1 = __expf(x.y - mxu[mt][h]) * inv[mt][h];
                    *(float2*)(attn + gidx) = make_float2(p0, p1);
                    float h0 = __bfloat162float(__float2bfloat16(p0));
                    float h1 = __bfloat162float(__float2bfloat16(p1));
                    *(uint32_t*)(sm + O_QH + (i * SB + j0) * 2) = pk2(p0, p1);
                    *(uint32_t*)(sm + O_QL + (i * SB + j0) * 2) = pk2(p0 - h0, p1 - h1);
                }
            }
        #pragma unroll
        for (int e = 0; e < 8; e++) {
            int f = tid + e * 128;
            int r = f >> 4, c4 = (f & 15) << 2;
            float4 vv = *(const float4*)(vb + (size_t)(t * 64 + r) * 64 + c4);
            spl(sm, O_KH, O_KL, r * SB + c4, vv);
        }
        __syncthreads();
        gemm3(O_QH, O_QL, O_KH, O_KL, accO, true);
        __syncthreads();
    }
    #pragma unroll
    for (int mt = 0; mt < 2; mt++)
        #pragma unroll
        for (int nf = 0; nf < 4; nf++) {
            int j0 = 32 * wc + 8 * nf + 2 * c2;
            #pragma unroll
            for (int h = 0; h < 2; h++) {
                int i = 32 * wr + 16 * mt + q4 + 8 * h;
                *(float2*)(out + ((size_t)b * L_ + l0 + i) * 64 + j0) =
                    make_float2(accO[mt][nf][2 * h], accO[mt][nf][2 * h + 1]);
            }
        }
}

extern "C" void kernel_launch(void* const* d_in, const int* in_sizes, int n_in,
                              void* d_out, int out_size) {
    const float* q = (const float*)d_in[0];
    const float* k = (const float*)d_in[1];
    const float* v = (const float*)d_in[2];
    const float* pos = (const float*)d_in[3];
    const char* msk = (const char*)d_in[4];
    float* out = (float*)d_out;
    float* attn = out + (size_t)B_ * L_ * 64;

    cudaFuncSetAttribute(fused_mma_kernel,
                         cudaFuncAttributeMaxDynamicSharedMemorySize, SMEMB);
    fused_mma_kernel<<<dim3(16, B_), 128, SMEMB>>>(q, k, v, pos, msk, out, attn);
}

// round 9
// speedup vs baseline: 1.2302x; 1.2230x over previous
#include <cuda_runtime.h>
#include <cuda_bf16.h>
#include <cstdint>
#include <math_constants.h>

#define B_ 64
#define L_ 1024
#define P_ 2047
#define SB 72          // smem tile stride (bf16 elems) = 144B rows
#define GS 68          // G buffer stride (floats)
#define NS 16

#define TILEB (64 * SB * 2)
#define O_QH 0
#define O_QL (O_QH + TILEB)
#define O_RH (O_QL + TILEB)
#define O_RL (O_RH + TILEB)
#define O_KH (O_RL + TILEB)
#define O_KL (O_KH + TILEB)
#define O_PH (O_KL + TILEB)
#define O_PL (O_PH + TILEB)
#define O_G  (O_PL + TILEB)
#define GSZ  (64 * GS)
#define O_ST (O_G + 2 * GSZ * 4)
#define O_MC (O_ST + 64 * 2 * 8)
#define SMEMB (O_MC + 16)

__device__ __forceinline__ uint32_t smem_u32(const void* p) {
    uint32_t a;
    asm("{ .reg .u64 t; cvta.to.shared.u64 t, %1; cvt.u32.u64 %0, t; }" : "=r"(a) : "l"(p));
    return a;
}
#define LDSM4(r, a) \
    asm volatile("ldmatrix.sync.aligned.m8n8.x4.shared.b16 {%0,%1,%2,%3}, [%4];" \
        : "=r"((r)[0]), "=r"((r)[1]), "=r"((r)[2]), "=r"((r)[3]) : "r"(a))
#define LDSM4T(r, a) \
    asm volatile("ldmatrix.sync.aligned.m8n8.x4.trans.shared.b16 {%0,%1,%2,%3}, [%4];" \
        : "=r"((r)[0]), "=r"((r)[1]), "=r"((r)[2]), "=r"((r)[3]) : "r"(a))
#define MMA(c, a, b) \
    asm volatile("mma.sync.aligned.m16n8k16.row.col.f32.bf16.bf16.f32 " \
        "{%0,%1,%2,%3}, {%4,%5,%6,%7}, {%8,%9}, {%0,%1,%2,%3};" \
        : "+f"((c)[0]), "+f"((c)[1]), "+f"((c)[2]), "+f"((c)[3]) \
        : "r"((a)[0]), "r"((a)[1]), "r"((a)[2]), "r"((a)[3]), "r"((b)[0]), "r"((b)[1]))

__device__ __forceinline__ uint32_t pk2(float a, float b) {
    return (uint32_t)__bfloat16_as_ushort(__float2bfloat16(a)) |
           ((uint32_t)__bfloat16_as_ushort(__float2bfloat16(b)) << 16);
}
__device__ __forceinline__ void spl(char* sm, int offH, int offL, int eo, float4 v) {
    float hx = __bfloat162float(__float2bfloat16(v.x));
    float hy = __bfloat162float(__float2bfloat16(v.y));
    float hz = __bfloat162float(__float2bfloat16(v.z));
    float hw = __bfloat162float(__float2bfloat16(v.w));
    *(uint2*)(sm + offH + eo * 2) = make_uint2(pk2(v.x, v.y), pk2(v.z, v.w));
    *(uint2*)(sm + offL + eo * 2) =
        make_uint2(pk2(v.x - hx, v.y - hy), pk2(v.z - hz, v.w - hw));
}
__device__ __forceinline__ void merge_ms(float& m, float& s, float om, float os) {
    float nm = fmaxf(m, om);
    float base = (nm == -CUDART_INF_F) ? 0.f : nm;
    s = s * __expf(m - base) + os * __expf(om - base);
    m = nm;
}

__global__ __launch_bounds__(256, 2)
void fused_mma_kernel(const float* __restrict__ q, const float* __restrict__ kk,
                      const float* __restrict__ v, const float* __restrict__ pos,
                      const char* __restrict__ maskp, float* __restrict__ out,
                      float* __restrict__ attn) {
    extern __shared__ char sm[];
    const uint32_t sb = smem_u32(sm);
    const int tid = threadIdx.x;
    const int lane = tid & 31, w = tid >> 5;
    const int wr = w & 3, wc = w >> 2;     // 4 warps in m (16 rows), 2 in n (32 cols)
    const int b = blockIdx.y, l0 = blockIdx.x * 64;

    const float* qb = q + (size_t)b * L_ * 64;
    const float* kb = kk + (size_t)b * L_ * 64;
    const float* vb = v + (size_t)b * L_ * 64;
    const float* pb = pos + (size_t)b * P_ * 64;

    float* ring = (float*)(sm + O_G);
    float2* st = (float2*)(sm + O_ST);
    int* cnt = (int*)(sm + O_MC);

    // ---- mask dtype detection (first 8KB) ----
    if (tid < 2) cnt[tid] = 0;
    __syncthreads();
    {
        int c0 = 0, c1 = 0;
        #pragma unroll
        for (int e = 0; e < 2; e++) {
            uint4 u = ((const uint4*)maskp)[tid * 2 + e];
            uint32_t ws[4] = {u.x, u.y, u.z, u.w};
            #pragma unroll
            for (int wd = 0; wd < 4; wd++) {
                c0 += ((ws[wd] & 0x000000ffu) != 0);
                c1 += ((ws[wd] & 0x0000ff00u) != 0);
            }
        }
        if (c0) atomicAdd(&cnt[0], c0);
        if (c1) atomicAdd(&cnt[1], c1);
    }

    // ---- prologue loads: Q, R (scaled 1/8), P win0, K0 ----
    {
        const int r = tid & 63, cb = tid >> 6;
        #pragma unroll
        for (int e = 0; e < 4; e++) {
            float4 a = *(const float4*)(qb + (size_t)(l0 + r) * 64 + cb * 16 + 4 * e);
            a.x *= .125f; a.y *= .125f; a.z *= .125f; a.w *= .125f;
            spl(sm, O_QH, O_QL, r * SB + cb * 16 + 4 * e, a);
            float4 rr = *(const float4*)(qb + (size_t)(L_ - 1 - (l0 + r)) * 64 + cb * 16 + 4 * e);
            rr.x *= .125f; rr.y *= .125f; rr.z *= .125f; rr.w *= .125f;
            spl(sm, O_RH, O_RL, r * SB + cb * 16 + 4 * e, rr);
            float4 kv = *(const float4*)(kb + (size_t)r * 64 + cb * 16 + 4 * e);
            spl(sm, O_KH, O_KL, r * SB + cb * 16 + 4 * e, kv);
            int pr = l0 + r; if (pr > P_ - 1) pr = P_ - 1;
            float4 pv = *(const float4*)(pb + (size_t)pr * 64 + cb * 16 + 4 * e);
            spl(sm, O_PH, O_PL, r * SB + cb * 16 + 4 * e, pv);
        }
    }
    __syncthreads();
    const int mode = (cnt[0] > 0 && cnt[1] > 0) ? 0 : 1;

    // A fragment (m16, own warp's rows)
    auto adA = [&](int off, int kc) -> uint32_t {
        return sb + off + ((16 * wr + (lane & 15)) * SB + kc * 16 + (lane >> 4) * 8) * 2;
    };
    // paired-n B fragment (n16 = two n8 frags per LDSM4)
    auto adB4 = [&](int off, int np, int kc) -> uint32_t {
        return sb + off + ((32 * wc + 16 * np + (lane >> 4) * 8 + (lane & 7)) * SB +
                           kc * 16 + ((lane >> 3) & 1) * 8) * 2;
    };
    auto adBT4 = [&](int off, int np, int kc) -> uint32_t {
        return sb + off + ((kc * 16 + (lane & 15)) * SB + 32 * wc + 16 * np + 8 * (lane >> 4)) * 2;
    };

    // 3-product split GEMM body with CACHED A fragments (paired B loads)
    auto gemm_cached = [&](const uint32_t (&Ah)[4][4], const uint32_t (&Al)[4][4],
                           int oBh, int oBl, float acc[4][4]) {
        #pragma unroll
        for (int kc = 0; kc < 4; kc++)
            #pragma unroll
            for (int np = 0; np < 2; np++) {
                uint32_t bh[4], bl[4];
                LDSM4(bh, adB4(oBh, np, kc));
                MMA(acc[2 * np], Ah[kc], bh);
                MMA(acc[2 * np], Al[kc], bh);
                MMA(acc[2 * np + 1], Ah[kc], bh + 2);
                MMA(acc[2 * np + 1], Al[kc], bh + 2);
                LDSM4(bl, adB4(oBl, np, kc));
                MMA(acc[2 * np], Ah[kc], bl);
                MMA(acc[2 * np + 1], Ah[kc], bl + 2);
            }
    };
    // 3-product split GEMM with A loaded from smem per kc
    auto gemm_load = [&](int oAh, int oAl, int oBh, int oBl, float acc[4][4], bool trans) {
        #pragma unroll
        for (int kc = 0; kc < 4; kc++) {
            uint32_t Ah[4], Al[4];
            LDSM4(Ah, adA(oAh, kc));
            LDSM4(Al, adA(oAl, kc));
            #pragma unroll
            for (int np = 0; np < 2; np++) {
                uint32_t bh[4], bl[4];
                if (trans) { LDSM4T(bh, adBT4(oBh, np, kc)); } else { LDSM4(bh, adB4(oBh, np, kc)); }
                MMA(acc[2 * np], Ah, bh);
                MMA(acc[2 * np], Al, bh);
                MMA(acc[2 * np + 1], Ah, bh + 2);
                MMA(acc[2 * np + 1], Al, bh + 2);
                if (trans) { LDSM4T(bl, adBT4(oBl, np, kc)); } else { LDSM4(bl, adB4(oBl, np, kc)); }
                MMA(acc[2 * np], Ah, bl);
                MMA(acc[2 * np + 1], Ah, bl + 2);
            }
        }
    };

    const int r0 = 16 * wr + (lane >> 2), c2 = lane & 3;

    auto ring_store = [&](float acc[4][4], int slot) {
        float* gn = ring + slot * GSZ;
        #pragma unroll
        for (int nf = 0; nf < 4; nf++) {
            int j0 = 32 * wc + 8 * nf + 2 * c2;
            #pragma unroll
            for (int h = 0; h < 2; h++) {
                int i = r0 + 8 * h;
                *(float2*)(gn + i * GS + j0) = make_float2(acc[nf][2 * h], acc[nf][2 * h + 1]);
            }
        }
    };
    auto load_P = [&](int win) {
        const int r = tid & 63, cb = tid >> 6;
        #pragma unroll
        for (int e = 0; e < 4; e++) {
            int pr = l0 + 64 * win + r; if (pr > P_ - 1) pr = P_ - 1;
            float4 pv = *(const float4*)(pb + (size_t)pr * 64 + cb * 16 + 4 * e);
            spl(sm, O_PH, O_PL, r * SB + cb * 16 + 4 * e, pv);
        }
    };

    // ---- persistent Q fragments (t-invariant A of the S GEMM) ----
    uint32_t Qh[4][4], Ql[4][4];
    #pragma unroll
    for (int kc = 0; kc < 4; kc++) { LDSM4(Qh[kc], adA(O_QH, kc)); LDSM4(Ql[kc], adA(O_QL, kc)); }

    // ---- prologue G0 = R @ P(win0)^T -> ring[0] ----
    {
        float accG[4][4] = {};
        gemm_load(O_RH, O_RL, O_PH, O_PL, accG, false);
        __syncthreads();
        ring_store(accG, 0);
        load_P(1);
        __syncthreads();
    }

    float run_m[2] = {-CUDART_INF_F, -CUDART_INF_F};
    float run_s[2] = {0.f, 0.f};

    // ================= phase 1: logits =================
    for (int t = 0; t < NS; t++) {
        float accS[4][4] = {};
        float accG[4][4] = {};
        gemm_cached(Qh, Ql, O_KH, O_KL, accS);
        gemm_load(O_RH, O_RL, O_PH, O_PL, accG, false);
        __syncthreads();                       // MMA reads of K/P complete
        ring_store(accG, (t + 1) & 1);
        if (t < NS - 1) {
            const int r = tid & 63, cb = tid >> 6;
            #pragma unroll
            for (int e = 0; e < 4; e++) {
                float4 kv = *(const float4*)(kb + (size_t)((t + 1) * 64 + r) * 64 + cb * 16 + 4 * e);
                spl(sm, O_KH, O_KL, r * SB + cb * 16 + 4 * e, kv);
            }
        }
        load_P(t + 2);
        __syncthreads();                       // ring + new tiles visible
        const float* gc = ring + (t & 1) * GSZ;
        const float* gn = ring + ((t + 1) & 1) * GSZ;
        float xv[2][8];
        #pragma unroll
        for (int nf = 0; nf < 4; nf++) {
            int j0 = 32 * wc + 8 * nf + 2 * c2;
            #pragma unroll
            for (int h = 0; h < 2; h++) {
                int i = r0 + 8 * h;
                int s0 = i + j0, s1 = s0 + 1;
                float x0 = accS[nf][2 * h] + ((s0 < 64) ? gc : gn)[i * GS + (s0 & 63)];
                float x1 = accS[nf][2 * h + 1] + ((s1 < 64) ? gc : gn)[i * GS + ((s1 & 63))];
                size_t gidx = ((size_t)b * L_ + l0 + i) * L_ + t * 64 + j0;
                if (mode == 0) {
                    unsigned short mv = *(const unsigned short*)(maskp + gidx);
                    if (mv & 0x00ff) x0 = -CUDART_INF_F;
                    if (mv & 0xff00) x1 = -CUDART_INF_F;
                } else {
                    uint2 mv = *(const uint2*)((const uint32_t*)maskp + gidx);
                    if (mv.x) x0 = -CUDART_INF_F;
                    if (mv.y) x1 = -CUDART_INF_F;
                }
                *(float2*)(attn + gidx) = make_float2(x0, x1);
                xv[h][2 * nf] = x0; xv[h][2 * nf + 1] = x1;
            }
        }
        #pragma unroll
        for (int h = 0; h < 2; h++) {
            float lm = xv[h][0];
            #pragma unroll
            for (int j = 1; j < 8; j++) lm = fmaxf(lm, xv[h][j]);
            float nm = fmaxf(run_m[h], lm);
            float base = (nm == -CUDART_INF_F) ? 0.f : nm;
            float es = 0.f;
            #pragma unroll
            for (int j = 0; j < 8; j++) es += __expf(xv[h][j] - base);
            run_s[h] = run_s[h] * __expf(run_m[h] - base) + es;
            run_m[h] = nm;
        }
    }

    // ---- merge stats: quad lanes then across the 2 wc warps ----
    #pragma unroll
    for (int h = 0; h < 2; h++) {
        #pragma unroll
        for (int sft = 1; sft < 4; sft <<= 1) {
            float om = __shfl_xor_sync(0xffffffffu, run_m[h], sft);
            float os = __shfl_xor_sync(0xffffffffu, run_s[h], sft);
            merge_ms(run_m[h], run_s[h], om, os);
        }
        if (c2 == 0) st[(r0 + 8 * h) * 2 + wc] = make_float2(run_m[h], run_s[h]);
    }
    __syncthreads();
    float mxu[2], inv[2];
    #pragma unroll
    for (int h = 0; h < 2; h++) {
        int i = r0 + 8 * h;
        float2 a = st[i * 2 + 0], bq = st[i * 2 + 1];
        float m = a.x, s = a.y;
        merge_ms(m, s, bq.x, bq.y);
        mxu[h] = (m == -CUDART_INF_F) ? 0.f : m;
        inv[h] = 1.f / s;
    }
    __syncthreads();

    // ================= phase 2: probs + O = P @ V =================
    float accO[4][4] = {};
    for (int t = 0; t < NS; t++) {
        #pragma unroll
        for (int nf = 0; nf < 4; nf++) {
            int j0 = 32 * wc + 8 * nf + 2 * c2;
            #pragma unroll
            for (int h = 0; h < 2; h++) {
                int i = r0 + 8 * h;
                size_t gidx = ((size_t)b * L_ + l0 + i) * L_ + t * 64 + j0;
                float2 x = *(const float2*)(attn + gidx);
                float p0 = __expf(x.x - mxu[h]) * inv[h];
                float p1 = __expf(x.y - mxu[h]) * inv[h];
                *(float2*)(attn + gidx) = make_float2(p0, p1);
                float h0 = __bfloat162float(__float2bfloat16(p0));
                float h1 = __bfloat162float(__float2bfloat16(p1));
                *(uint32_t*)(sm + O_QH + (i * SB + j0) * 2) = pk2(p0, p1);
                *(uint32_t*)(sm + O_QL + (i * SB + j0) * 2) = pk2(p0 - h0, p1 - h1);
            }
        }
        {
            const int r = tid & 63, cb = tid >> 6;
            #pragma unroll
            for (int e = 0; e < 4; e++) {
                float4 vv = *(const float4*)(vb + (size_t)(t * 64 + r) * 64 + cb * 16 + 4 * e);
                spl(sm, O_KH, O_KL, r * SB + cb * 16 + 4 * e, vv);
            }
        }
        __syncthreads();
        gemm_load(O_QH, O_QL, O_KH, O_KL, accO, true);
        __syncthreads();
    }
    // ---- store O ----
    #pragma unroll
    for (int nf = 0; nf < 4; nf++) {
        int j0 = 32 * wc + 8 * nf + 2 * c2;
        #pragma unroll
        for (int h = 0; h < 2; h++) {
            int i = r0 + 8 * h;
            *(float2*)(out + ((size_t)b * L_ + l0 + i) * 64 + j0) =
                make_float2(accO[nf][2 * h], accO[nf][2 * h + 1]);
        }
    }
}

extern "C" void kernel_launch(void* const* d_in, const int* in_sizes, int n_in,
                              void* d_out, int out_size) {
    const float* q = (const float*)d_in[0];
    const float* k = (const float*)d_in[1];
    const float* v = (const float*)d_in[2];
    const float* pos = (const float*)d_in[3];
    const char* msk = (const char*)d_in[4];
    float* out = (float*)d_out;
    float* attn = out + (size_t)B_ * L_ * 64;

    cudaFuncSetAttribute(fused_mma_kernel,
                         cudaFuncAttributeMaxDynamicSharedMemorySize, SMEMB);
    fused_mma_kernel<<<dim3(16, B_), 256, SMEMB>>>(q, k, v, pos, msk, out, attn);
}

// round 10
// speedup vs baseline: 1.2799x; 1.0404x over previous
#include <cuda_runtime.h>
#include <cuda_bf16.h>
#include <cstdint>
#include <math_constants.h>

#define B_ 64
#define L_ 1024
#define P_ 2047
#define NS 16
#define SBI 272                 // interleaved tile row stride (bytes): 8 blocks x [16B hi|16B lo] + 16B pad
#define TI  (64 * SBI)          // 17408 B per 64-row tile
#define GS  72                  // ring stride (floats)

#define O_Q  0
#define O_R  (O_Q + TI)
#define O_K  (O_R + TI)
#define O_P  (O_K + TI)
#define O_G  (O_P + TI)
#define GSZ  (64 * GS)
#define O_ST (O_G + 2 * GSZ * 4)
#define O_MC (O_ST + 64 * 2 * 8)
#define SMEMB (O_MC + 16)

__device__ __forceinline__ uint32_t smem_u32(const void* p) {
    uint32_t a;
    asm("{ .reg .u64 t; cvta.to.shared.u64 t, %1; cvt.u32.u64 %0, t; }" : "=r"(a) : "l"(p));
    return a;
}
#define LDSM4(r, a) \
    asm volatile("ldmatrix.sync.aligned.m8n8.x4.shared.b16 {%0,%1,%2,%3}, [%4];" \
        : "=r"((r)[0]), "=r"((r)[1]), "=r"((r)[2]), "=r"((r)[3]) : "r"(a))
#define LDSM4T(r, a) \
    asm volatile("ldmatrix.sync.aligned.m8n8.x4.trans.shared.b16 {%0,%1,%2,%3}, [%4];" \
        : "=r"((r)[0]), "=r"((r)[1]), "=r"((r)[2]), "=r"((r)[3]) : "r"(a))
#define MMA(c, a, b) \
    asm volatile("mma.sync.aligned.m16n8k16.row.col.f32.bf16.bf16.f32 " \
        "{%0,%1,%2,%3}, {%4,%5,%6,%7}, {%8,%9}, {%0,%1,%2,%3};" \
        : "+f"((c)[0]), "+f"((c)[1]), "+f"((c)[2]), "+f"((c)[3]) \
        : "r"((a)[0]), "r"((a)[1]), "r"((a)[2]), "r"((a)[3]), "r"((b)[0]), "r"((b)[1]))

__device__ __forceinline__ uint32_t pk2(float a, float b) {
    return (uint32_t)__bfloat16_as_ushort(__float2bfloat16(a)) |
           ((uint32_t)__bfloat16_as_ushort(__float2bfloat16(b)) << 16);
}
__device__ __forceinline__ float bfres(float x) {
    return x - __bfloat162float(__float2bfloat16(x));
}
// store one 8-elem k-block (hi 16B + lo 16B) of row r
__device__ __forceinline__ void st_blk(char* sm, int oT, int r, int bl, float4 a, float4 b) {
    uint4 hi = make_uint4(pk2(a.x, a.y), pk2(a.z, a.w), pk2(b.x, b.y), pk2(b.z, b.w));
    uint4 lo = make_uint4(pk2(bfres(a.x), bfres(a.y)), pk2(bfres(a.z), bfres(a.w)),
                          pk2(bfres(b.x), bfres(b.y)), pk2(bfres(b.z), bfres(b.w)));
    char* p = sm + oT + r * SBI + bl * 32;
    *(uint4*)p = hi;
    *(uint4*)(p + 16) = lo;
}
__device__ __forceinline__ void merge_ms(float& m, float& s, float om, float os) {
    float nm = fmaxf(m, om);
    float base = (nm == -CUDART_INF_F) ? 0.f : nm;
    s = s * __expf(m - base) + os * __expf(om - base);
    m = nm;
}

__global__ __launch_bounds__(256, 2)
void fused_mma_kernel(const float* __restrict__ q, const float* __restrict__ kk,
                      const float* __restrict__ v, const float* __restrict__ pos,
                      const char* __restrict__ maskp, float* __restrict__ out,
                      float* __restrict__ attn) {
    extern __shared__ char sm[];
    const uint32_t sb = smem_u32(sm);
    const int tid = threadIdx.x;
    const int lane = tid & 31, w = tid >> 5;
    const int wr = w & 3, wc = w >> 2;     // 4 warps in m (16 rows), 2 in n/k (32)
    const int b = blockIdx.y, l0 = blockIdx.x * 64;

    const float* qb = q + (size_t)b * L_ * 64;
    const float* kb = kk + (size_t)b * L_ * 64;
    const float* vb = v + (size_t)b * L_ * 64;
    const float* pb = pos + (size_t)b * P_ * 64;

    float* ring = (float*)(sm + O_G);
    float2* st = (float2*)(sm + O_ST);
    int* cnt = (int*)(sm + O_MC);

    // ---- mask dtype detection (first 8KB) ----
    if (tid < 2) cnt[tid] = 0;
    __syncthreads();
    {
        int c0 = 0, c1 = 0;
        #pragma unroll
        for (int e = 0; e < 2; e++) {
            uint4 u = ((const uint4*)maskp)[tid * 2 + e];
            uint32_t ws[4] = {u.x, u.y, u.z, u.w};
            #pragma unroll
            for (int wd = 0; wd < 4; wd++) {
                c0 += ((ws[wd] & 0x000000ffu) != 0);
                c1 += ((ws[wd] & 0x0000ff00u) != 0);
            }
        }
        if (c0) atomicAdd(&cnt[0], c0);
        if (c1) atomicAdd(&cnt[1], c1);
    }

    // ---- tile fill helpers (2 tasks/thread, 8 consecutive k-elems each) ----
    auto fill_QR = [&]() {
        #pragma unroll
        for (int e = 0; e < 2; e++) {
            int tt = tid + e * 256, r = tt & 63, bl = tt >> 6;
            const float* ap = qb + (size_t)(l0 + r) * 64 + bl * 8;
            float4 a0 = *(const float4*)ap, a1 = *(const float4*)(ap + 4);
            a0.x *= .125f; a0.y *= .125f; a0.z *= .125f; a0.w *= .125f;
            a1.x *= .125f; a1.y *= .125f; a1.z *= .125f; a1.w *= .125f;
            st_blk(sm, O_Q, r, bl, a0, a1);
            const float* rp = qb + (size_t)(L_ - 1 - (l0 + r)) * 64 + bl * 8;
            float4 r0v = *(const float4*)rp, r1v = *(const float4*)(rp + 4);
            r0v.x *= .125f; r0v.y *= .125f; r0v.z *= .125f; r0v.w *= .125f;
            r1v.x *= .125f; r1v.y *= .125f; r1v.z *= .125f; r1v.w *= .125f;
            st_blk(sm, O_R, r, bl, r0v, r1v);
        }
    };
    auto fill_K = [&](int t) {
        #pragma unroll
        for (int e = 0; e < 2; e++) {
            int tt = tid + e * 256, r = tt & 63, bl = tt >> 6;
            const float* ap = kb + (size_t)(t * 64 + r) * 64 + bl * 8;
            st_blk(sm, O_K, r, bl, *(const float4*)ap, *(const float4*)(ap + 4));
        }
    };
    auto fill_V = [&](int t) {
        #pragma unroll
        for (int e = 0; e < 2; e++) {
            int tt = tid + e * 256, r = tt & 63, bl = tt >> 6;
            const float* ap = vb + (size_t)(t * 64 + r) * 64 + bl * 8;
            st_blk(sm, O_K, r, bl, *(const float4*)ap, *(const float4*)(ap + 4));
        }
    };
    auto fill_P = [&](int win) {
        #pragma unroll
        for (int e = 0; e < 2; e++) {
            int tt = tid + e * 256, r = tt & 63, bl = tt >> 6;
            int pr = l0 + 64 * win + r; if (pr > P_ - 1) pr = P_ - 1;
            const float* ap = pb + (size_t)pr * 64 + bl * 8;
            st_blk(sm, O_P, r, bl, *(const float4*)ap, *(const float4*)(ap + 4));
        }
    };

    fill_QR(); fill_K(0); fill_P(0);
    __syncthreads();
    const int mode = (cnt[0] > 0 && cnt[1] > 0) ? 0 : 1;

    // ---- fragment address helpers (interleaved layout) ----
    auto adA = [&](int oT, int kc, int hi) -> uint32_t {
        int row = 16 * wr + (lane & 15), blk = 2 * kc + (lane >> 4);
        return sb + oT + row * SBI + blk * 32 + (hi ? 0 : 16);
    };
    auto adB = [&](int oT, int np, int kc, int hi) -> uint32_t {
        int nrow = 32 * wc + 16 * np + 8 * (lane >> 4) + (lane & 7);
        int blk = 2 * kc + ((lane >> 3) & 1);
        return sb + oT + nrow * SBI + blk * 32 + (hi ? 0 : 16);
    };
    auto adBT = [&](int oT, int np, int kc2, int hi) -> uint32_t {
        int krow = 32 * wc + 16 * kc2 + (lane & 15);
        int blk = 2 * np + (lane >> 4);
        return sb + oT + krow * SBI + blk * 32 + (hi ? 0 : 16);
    };

    const int r0 = 16 * wr + (lane >> 2), c2 = lane & 3;

    // ---- persistent fragments: Q hi+lo, R hi ----
    uint32_t Qh[4][4], Ql[4][4], Rh[4][4];
    #pragma unroll
    for (int kc = 0; kc < 4; kc++) {
        LDSM4(Qh[kc], adA(O_Q, kc, 1));
        LDSM4(Ql[kc], adA(O_Q, kc, 0));
        LDSM4(Rh[kc], adA(O_R, kc, 1));
    }

    auto gemm_S = [&](float acc[4][4]) {
        #pragma unroll
        for (int kc = 0; kc < 4; kc++)
            #pragma unroll
            for (int np = 0; np < 2; np++) {
                uint32_t bh[4], bl_[4];
                LDSM4(bh, adB(O_K, np, kc, 1));
                MMA(acc[2 * np], Qh[kc], bh);     MMA(acc[2 * np], Ql[kc], bh);
                MMA(acc[2 * np + 1], Qh[kc], bh + 2); MMA(acc[2 * np + 1], Ql[kc], bh + 2);
                LDSM4(bl_, adB(O_K, np, kc, 0));
                MMA(acc[2 * np], Qh[kc], bl_);    MMA(acc[2 * np + 1], Qh[kc], bl_ + 2);
            }
    };
    auto gemm_G = [&](float acc[4][4]) {
        #pragma unroll
        for (int kc = 0; kc < 4; kc++) {
            uint32_t rl[4];
            LDSM4(rl, adA(O_R, kc, 0));
            #pragma unroll
            for (int np = 0; np < 2; np++) {
                uint32_t bh[4], bl_[4];
                LDSM4(bh, adB(O_P, np, kc, 1));
                MMA(acc[2 * np], Rh[kc], bh);     MMA(acc[2 * np], rl, bh);
                MMA(acc[2 * np + 1], Rh[kc], bh + 2); MMA(acc[2 * np + 1], rl, bh + 2);
                LDSM4(bl_, adB(O_P, np, kc, 0));
                MMA(acc[2 * np], Rh[kc], bl_);    MMA(acc[2 * np + 1], Rh[kc], bl_ + 2);
            }
        }
    };
    auto ring_store = [&](float acc[4][4], int slot) {
        float* gn = ring + slot * GSZ;
        #pragma unroll
        for (int nf = 0; nf < 4; nf++) {
            int j0 = 32 * wc + 8 * nf + 2 * c2;
            #pragma unroll
            for (int h = 0; h < 2; h++) {
                int i = r0 + 8 * h;
                *(float2*)(gn + i * GS + j0) = make_float2(acc[nf][2 * h], acc[nf][2 * h + 1]);
            }
        }
    };

    // ---- prologue G0 ----
    {
        float accG[4][4] = {};
        gemm_G(accG);
        __syncthreads();
        ring_store(accG, 0);
        fill_P(1);
        __syncthreads();
    }

    float run_m[2] = {-CUDART_INF_F, -CUDART_INF_F};
    float run_s[2] = {0.f, 0.f};

    // ================= phase 1: logits =================
    for (int t = 0; t < NS; t++) {
        float accS[4][4] = {};
        float accG[4][4] = {};
        gemm_S(accS);
        gemm_G(accG);
        __syncthreads();
        ring_store(accG, (t + 1) & 1);
        if (t < NS - 1) fill_K(t + 1);
        fill_P(t + 2);
        __syncthreads();
        const float* gc = ring + (t & 1) * GSZ;
        const float* gn = ring + ((t + 1) & 1) * GSZ;
        float xv[2][8];
        #pragma unroll
        for (int nf = 0; nf < 4; nf++) {
            int j0 = 32 * wc + 8 * nf + 2 * c2;
            #pragma unroll
            for (int h = 0; h < 2; h++) {
                int i = r0 + 8 * h;
                int s0 = i + j0, s1 = s0 + 1;
                float x0 = accS[nf][2 * h] + ((s0 < 64) ? gc : gn)[i * GS + (s0 & 63)];
                float x1 = accS[nf][2 * h + 1] + ((s1 < 64) ? gc : gn)[i * GS + (s1 & 63)];
                size_t gidx = ((size_t)b * L_ + l0 + i) * L_ + t * 64 + j0;
                if (mode == 0) {
                    unsigned short mv = *(const unsigned short*)(maskp + gidx);
                    if (mv & 0x00ff) x0 = -CUDART_INF_F;
                    if (mv & 0xff00) x1 = -CUDART_INF_F;
                } else {
                    uint2 mv = *(const uint2*)((const uint32_t*)maskp + gidx);
                    if (mv.x) x0 = -CUDART_INF_F;
                    if (mv.y) x1 = -CUDART_INF_F;
                }
                *(float2*)(attn + gidx) = make_float2(x0, x1);
                xv[h][2 * nf] = x0; xv[h][2 * nf + 1] = x1;
            }
        }
        #pragma unroll
        for (int h = 0; h < 2; h++) {
            float lm = xv[h][0];
            #pragma unroll
            for (int j = 1; j < 8; j++) lm = fmaxf(lm, xv[h][j]);
            float nm = fmaxf(run_m[h], lm);
            float base = (nm == -CUDART_INF_F) ? 0.f : nm;
            float es = 0.f;
            #pragma unroll
            for (int j = 0; j < 8; j++) es += __expf(xv[h][j] - base);
            run_s[h] = run_s[h] * __expf(run_m[h] - base) + es;
            run_m[h] = nm;
        }
    }

    // ---- merge stats ----
    #pragma unroll
    for (int h = 0; h < 2; h++) {
        #pragma unroll
        for (int sft = 1; sft < 4; sft <<= 1) {
            float om = __shfl_xor_sync(0xffffffffu, run_m[h], sft);
            float os = __shfl_xor_sync(0xffffffffu, run_s[h], sft);
            merge_ms(run_m[h], run_s[h], om, os);
        }
        if (c2 == 0) st[(r0 + 8 * h) * 2 + wc] = make_float2(run_m[h], run_s[h]);
    }
    __syncthreads();
    float mxu[2], inv[2];
    #pragma unroll
    for (int h = 0; h < 2; h++) {
        int i = r0 + 8 * h;
        float2 a = st[i * 2 + 0], bq = st[i * 2 + 1];
        float m = a.x, s = a.y;
        merge_ms(m, s, bq.x, bq.y);
        mxu[h] = (m == -CUDART_INF_F) ? 0.f : m;
        inv[h] = 1.f / s;
    }
    __syncthreads();

    // ========= phase 2: probs + O = P @ V (P in registers, split-k by wc) =========
    float accO[8][4] = {};
    for (int t = 0; t < NS; t++) {
        uint32_t Ph[2][4], Pl[2][4];
        #pragma unroll
        for (int nf = 0; nf < 4; nf++) {
            int j0 = 32 * wc + 8 * nf + 2 * c2;
            #pragma unroll
            for (int h = 0; h < 2; h++) {
                int i = r0 + 8 * h;
                size_t gidx = ((size_t)b * L_ + l0 + i) * L_ + t * 64 + j0;
                float2 x = *(const float2*)(attn + gidx);
                float p0 = __expf(x.x - mxu[h]) * inv[h];
                float p1 = __expf(x.y - mxu[h]) * inv[h];
                *(float2*)(attn + gidx) = make_float2(p0, p1);
                int reg = 2 * (nf & 1) + h;
                Ph[nf >> 1][reg] = pk2(p0, p1);
                Pl[nf >> 1][reg] = pk2(bfres(p0), bfres(p1));
            }
        }
        fill_V(t);
        __syncthreads();
        #pragma unroll
        for (int kc2 = 0; kc2 < 2; kc2++)
            #pragma unroll
            for (int np = 0; np < 4; np++) {
                uint32_t bh[4], bl_[4];
                LDSM4T(bh, adBT(O_K, np, kc2, 1));
                MMA(accO[2 * np], Ph[kc2], bh);     MMA(accO[2 * np], Pl[kc2], bh);
                MMA(accO[2 * np + 1], Ph[kc2], bh + 2); MMA(accO[2 * np + 1], Pl[kc2], bh + 2);
                LDSM4T(bl_, adBT(O_K, np, kc2, 0));
                MMA(accO[2 * np], Ph[kc2], bl_);    MMA(accO[2 * np + 1], Ph[kc2], bl_ + 2);
            }
        __syncthreads();
    }
    // ---- split-k reduction (wc=0 partial -> smem; wc=1 adds and stores) ----
    if (wc == 0) {
        #pragma unroll
        for (int g = 0; g < 8; g++) {
            int j0 = 8 * g + 2 * c2;
            #pragma unroll
            for (int h = 0; h < 2; h++)
                *(float2*)(ring + (r0 + 8 * h) * GS + j0) =
                    make_float2(accO[g][2 * h], accO[g][2 * h + 1]);
        }
    }
    __syncthreads();
    if (wc == 1) {
        #pragma unroll
        for (int g = 0; g < 8; g++) {
            int j0 = 8 * g + 2 * c2;
            #pragma unroll
            for (int h = 0; h < 2; h++) {
                int i = r0 + 8 * h;
                float2 pp = *(const float2*)(ring + i * GS + j0);
                *(float2*)(out + ((size_t)b * L_ + l0 + i) * 64 + j0) =
                    make_float2(accO[g][2 * h] + pp.x, accO[g][2 * h + 1] + pp.y);
            }
        }
    }
}

extern "C" void kernel_launch(void* const* d_in, const int* in_sizes, int n_in,
                              void* d_out, int out_size) {
    const float* q = (const float*)d_in[0];
    const float* k = (const float*)d_in[1];
    const float* v = (const float*)d_in[2];
    const float* pos = (const float*)d_in[3];
    const char* msk = (const char*)d_in[4];
    float* out = (float*)d_out;
    float* attn = out + (size_t)B_ * L_ * 64;

    cudaFuncSetAttribute(fused_mma_kernel,
                         cudaFuncAttributeMaxDynamicSharedMemorySize, SMEMB);
    fused_mma_kernel<<<dim3(16, B_), 256, SMEMB>>>(q, k, v, pos, msk, out, attn);
}